// round 1
// baseline (speedup 1.0000x reference)
#include <cuda_runtime.h>
#include <math.h>

#define NB 8
#define NC 64
#define NG 4
#define CG 16
#define NH 128
#define NW 128
#define HW (NH*NW)
#define IMG (NB*NC*HW)      // 8388608
#define NROW (NB*NH)        // 1024

// ---------------- scratch (device globals; no runtime allocation) ----------
__device__ float g_t1[IMG];
__device__ float g_t2[IMG];
__device__ float g_Q[(size_t)NROW*NW*NC];
__device__ float g_K[(size_t)NROW*NW*NC];
__device__ float g_bnA[2][NC];
__device__ float g_bnB[2][NC];

// ---------------- BN statistics (training mode, per image) -----------------
__global__ __launch_bounds__(256) void bn_stats_kernel(
    const float* __restrict__ xl, const float* __restrict__ xr,
    const float* __restrict__ gamma, const float* __restrict__ beta) {
  int c = blockIdx.x & 63;
  int img = blockIdx.x >> 6;
  const float* x = img ? xr : xl;
  int t = threadIdx.x;
  float s = 0.f, s2 = 0.f;
  for (int b = 0; b < NB; b++) {
    const float* p = x + (size_t)(b*NC + c)*HW;
    for (int i = t; i < HW; i += 256) { float v = p[i]; s += v; s2 += v*v; }
  }
  __shared__ float sh[256], sh2[256];
  sh[t] = s; sh2[t] = s2; __syncthreads();
  for (int off = 128; off; off >>= 1) {
    if (t < off) { sh[t] += sh[t+off]; sh2[t] += sh2[t+off]; }
    __syncthreads();
  }
  if (t == 0) {
    const float inv = 1.f / (float)(NB*HW);
    float mean = sh[0] * inv;
    float var  = sh2[0] * inv - mean*mean;
    float a = gamma[c] * rsqrtf(var + 1e-5f);
    g_bnA[img][c] = a;
    g_bnB[img][c] = beta[c] - mean * a;
  }
}

// ---------------- grouped 3x3 conv -----------------------------------------
// BN_IN: apply BN affine to the input while staging (conv1 of resb)
// RES  : add bias + BN(x_orig) residual, no activation (conv2 of resb)
// !RES : LeakyReLU(0.1) on output (conv1 of resb)
#define IN_ST 130
#define CONV_SMEM ((CG*6*IN_ST + CG*CG*9)*4)

template<bool BN_IN, bool RES>
__global__ __launch_bounds__(256) void conv3x3_kernel(
    const float* __restrict__ xin, const float* __restrict__ xres,
    const float* __restrict__ wgt, const float* __restrict__ bias,
    float* __restrict__ out, int img) {
  extern __shared__ float sm[];
  float* in_s = sm;                 // [16][6][130]
  float* w_s  = sm + CG*6*IN_ST;    // [16oc][16ic][9]
  int t = threadIdx.x;
  int b = blockIdx.y >> 2, g = blockIdx.y & 3;
  int h0 = blockIdx.x * 4;

  for (int i = t; i < CG*CG*9; i += 256) w_s[i] = wgt[g*CG*CG*9 + i];

  for (int i = t; i < CG*6*IN_ST; i += 256) {
    int ic  = i / (6*IN_ST);
    int rem = i - ic*6*IN_ST;
    int r   = rem / IN_ST;
    int wc  = rem - r*IN_ST;
    int hh  = h0 - 1 + r;
    int ww  = wc - 1;
    float v = 0.f;
    if ((unsigned)hh < NH && (unsigned)ww < NW) {
      v = xin[((size_t)(b*NC + g*CG + ic)*NH + hh)*NW + ww];
      if (BN_IN) v = g_bnA[img][g*CG+ic]*v + g_bnB[img][g*CG+ic];
    }
    in_s[i] = v;
  }
  __syncthreads();

  int wseg = t & 15, hh = (t >> 4) & 3, ocq = t >> 6;
  int w0 = wseg * 8, oc0 = ocq * 4;
  float acc[4][8];
  #pragma unroll
  for (int o = 0; o < 4; o++) {
    float bz = bias[g*CG + oc0 + o];
    #pragma unroll
    for (int j = 0; j < 8; j++) acc[o][j] = bz;
  }

  for (int ic = 0; ic < CG; ic++) {
    #pragma unroll
    for (int kh = 0; kh < 3; kh++) {
      const float* row = in_s + (ic*6 + hh + kh)*IN_ST + w0;
      float in[10];
      #pragma unroll
      for (int j = 0; j < 10; j++) in[j] = row[j];
      #pragma unroll
      for (int o = 0; o < 4; o++) {
        const float* wp = w_s + (oc0+o)*(CG*9) + ic*9 + kh*3;
        float wa = wp[0], wb = wp[1], wc2 = wp[2];
        #pragma unroll
        for (int j = 0; j < 8; j++)
          acc[o][j] += wa*in[j] + wb*in[j+1] + wc2*in[j+2];
      }
    }
  }

  int hout = h0 + hh;
  #pragma unroll
  for (int o = 0; o < 4; o++) {
    int ch = g*CG + oc0 + o;
    size_t base = ((size_t)(b*NC + ch)*NH + hout)*NW + w0;
    float ra = RES ? g_bnA[img][ch] : 0.f;
    float rb = RES ? g_bnB[img][ch] : 0.f;
    #pragma unroll
    for (int j = 0; j < 8; j++) {
      float v = acc[o][j];
      if (!RES) v = v > 0.f ? v : 0.1f*v;        // LeakyReLU(0.1)
      else      v += ra*xres[base+j] + rb;        // + BN(x) residual
      out[base+j] = v;
    }
  }
}

// ---------------- grouped 1x1 conv + row-mean subtract -> NHWC -------------
#define QK_SMEM ((NC*NW + NC*129)*4)
__global__ __launch_bounds__(256) void qk_kernel(
    const float* __restrict__ xin, const float* __restrict__ wgt,
    const float* __restrict__ bias, float* __restrict__ outg) {
  extern __shared__ float sm[];
  float* in_s  = sm;            // [64][128]
  float* out_s = sm + NC*NW;    // [64][129]
  int n = blockIdx.x, b = n >> 7, h = n & 127;
  int t = threadIdx.x;

  for (int i = t; i < NC*NW; i += 256) {
    int c = i >> 7, wv = i & 127;
    in_s[i] = xin[((size_t)(b*NC + c)*NH + h)*NW + wv];
  }
  __syncthreads();

  for (int i = t; i < NC*NW; i += 256) {
    int c = i >> 7, wv = i & 127;
    int g = c >> 4;
    float a = bias[c];
    const float* wp = wgt + c*CG;
    #pragma unroll
    for (int ic = 0; ic < CG; ic++) a += wp[ic]*in_s[(g*CG+ic)*NW + wv];
    out_s[c*129 + wv] = a;
  }
  __syncthreads();

  int warp = t >> 5, lane = t & 31;
  for (int c = warp; c < NC; c += 8) {
    float s = 0.f;
    for (int wv = lane; wv < NW; wv += 32) s += out_s[c*129 + wv];
    #pragma unroll
    for (int off = 16; off; off >>= 1) s += __shfl_xor_sync(0xffffffffu, s, off);
    float mean = s * (1.f/128.f);
    for (int wv = lane; wv < NW; wv += 32) out_s[c*129 + wv] -= mean;
  }
  __syncthreads();

  for (int i = t; i < NC*NW; i += 256) {
    int wv = i >> 6, c = i & 63;
    outg[(size_t)n*NW*NC + i] = out_s[c*129 + wv];   // [n][w][c], coalesced
  }
}

// ---------------- fused attention: S, softmaxes, m_relax/V, transforms -----
#define ST 132
#define XST 66
#define ATTN_SMEM ((3*128*ST + 6*128)*4)   // 205824 bytes

__global__ __launch_bounds__(256) void attn_kernel(
    const float* __restrict__ xL, const float* __restrict__ xR,
    float* __restrict__ outL, float* __restrict__ outR) {
  extern __shared__ float sm[];
  float* Am = sm;                 // S -> later xl/xr rows (stride 66)
  float* Bm = Am + 128*ST;        // Qt/Kt -> later Qm[a][b] = M_lr[b][a]
  float* Cm = Bm + 128*ST;        // P[v][u] = M_rl[u][v]
  float* rmax  = Cm + 128*ST;
  float* rsumI = rmax + 128;
  float* cmax  = rsumI + 128;
  float* csumI = cmax + 128;
  float* Vl    = csumI + 128;
  float* Vr    = Vl + 128;
  int n = blockIdx.x, b = n >> 7, h = n & 127;
  int t = threadIdx.x;
  int warp = t >> 5, lane = t & 31;

  // stage Qt[k][u], Kt[k][v]
  const float* Qp = g_Q + (size_t)n*8192;
  const float* Kp = g_K + (size_t)n*8192;
  for (int i = t; i < 8192; i += 256) {
    int u = i >> 6, k = i & 63;
    Bm[k*ST + u]        = Qp[i];
    Bm[(64+k)*ST + u]   = Kp[i];
  }
  __syncthreads();

  // GEMM1: S[u][v] = sum_k Qt[k][u]*Kt[k][v]   (8x8 per thread)
  int ut = t >> 4, vt = t & 15;
  int u0 = ut*8, v0 = vt*8;
  {
    float acc[8][8];
    #pragma unroll
    for (int i = 0; i < 8; i++)
      #pragma unroll
      for (int j = 0; j < 8; j++) acc[i][j] = 0.f;
    for (int k = 0; k < 64; k++) {
      float4 qa = *(const float4*)&Bm[k*ST + u0];
      float4 qb = *(const float4*)&Bm[k*ST + u0 + 4];
      float4 ka = *(const float4*)&Bm[(64+k)*ST + v0];
      float4 kb = *(const float4*)&Bm[(64+k)*ST + v0 + 4];
      float q[8] = {qa.x,qa.y,qa.z,qa.w,qb.x,qb.y,qb.z,qb.w};
      float kk[8] = {ka.x,ka.y,ka.z,ka.w,kb.x,kb.y,kb.z,kb.w};
      #pragma unroll
      for (int i = 0; i < 8; i++)
        #pragma unroll
        for (int j = 0; j < 8; j++) acc[i][j] += q[i]*kk[j];
    }
    #pragma unroll
    for (int i = 0; i < 8; i++) {
      *(float4*)&Am[(u0+i)*ST + v0]     = make_float4(acc[i][0],acc[i][1],acc[i][2],acc[i][3]);
      *(float4*)&Am[(u0+i)*ST + v0 + 4] = make_float4(acc[i][4],acc[i][5],acc[i][6],acc[i][7]);
    }
  }
  __syncthreads();

  // row softmax stats (M_rl) and column stats (M_lr)
  for (int u = warp; u < 128; u += 8) {
    float m = -1e30f;
    for (int j = lane; j < 128; j += 32) m = fmaxf(m, Am[u*ST + j]);
    #pragma unroll
    for (int off = 16; off; off >>= 1) m = fmaxf(m, __shfl_xor_sync(0xffffffffu, m, off));
    float s = 0.f;
    for (int j = lane; j < 128; j += 32) s += __expf(Am[u*ST + j] - m);
    #pragma unroll
    for (int off = 16; off; off >>= 1) s += __shfl_xor_sync(0xffffffffu, s, off);
    if (lane == 0) { rmax[u] = m; rsumI[u] = 1.f / s; }
  }
  for (int j = warp; j < 128; j += 8) {
    float m = -1e30f;
    for (int u2 = lane; u2 < 128; u2 += 32) m = fmaxf(m, Am[u2*ST + j]);
    #pragma unroll
    for (int off = 16; off; off >>= 1) m = fmaxf(m, __shfl_xor_sync(0xffffffffu, m, off));
    float s = 0.f;
    for (int u2 = lane; u2 < 128; u2 += 32) s += __expf(Am[u2*ST + j] - m);
    #pragma unroll
    for (int off = 16; off; off >>= 1) s += __shfl_xor_sync(0xffffffffu, s, off);
    if (lane == 0) { cmax[j] = m; csumI[j] = 1.f / s; }
  }
  __syncthreads();

  // Qm[a][b] = M_lr[b][a] = exp(S[a][b]-cmax[b])*csumI[b]   (into Bm)
  // P [v][u] = M_rl[u][v] = exp(S[u][v]-rmax[u])*rsumI[u]   (into Cm)
  for (int i = t; i < 16384; i += 256) {
    int r = i >> 7, cI = i & 127;
    Bm[r*ST + cI] = __expf(Am[r*ST + cI] - cmax[cI]) * csumI[cI];
    Cm[r*ST + cI] = __expf(Am[cI*ST + r] - rmax[cI]) * rsumI[cI];
  }
  __syncthreads();

  // load x rows into Am (S is dead): xl_s[v][c], xr_s[v][c], stride 66
  float* xls = Am;
  float* xrs = Am + 128*XST;
  for (int i = t; i < 8192; i += 256) {
    int c = i >> 7, v = i & 127;
    xls[v*XST + c] = xL[((size_t)(b*NC + c)*NH + h)*NW + v];
    xrs[v*XST + c] = xR[((size_t)(b*NC + c)*NH + h)*NW + v];
  }

  // V_left[u]  = sum_v (sum_i P[v][u+i])  * Qm[u][v]
  // V_right[u] = sum_v (sum_i Qm[v][u+i]) * P[u][v]
  for (int u = warp; u < 128; u += 8) {
    float vl = 0.f, vr = 0.f;
    for (int v = lane; v < 128; v += 32) {
      float pa = 0.f, qa = 0.f;
      #pragma unroll
      for (int i2 = -2; i2 <= 2; i2++) {
        int ui = u + i2;
        if ((unsigned)ui < 128u) { pa += Cm[v*ST + ui]; qa += Bm[v*ST + ui]; }
      }
      vl += pa * Bm[u*ST + v];
      vr += qa * Cm[u*ST + v];
    }
    #pragma unroll
    for (int off = 16; off; off >>= 1) {
      vl += __shfl_xor_sync(0xffffffffu, vl, off);
      vr += __shfl_xor_sync(0xffffffffu, vr, off);
    }
    if (lane == 0) { Vl[u] = tanhf(5.f*vl); Vr[u] = tanhf(5.f*vr); }
  }
  __syncthreads();

  // GEMM2/3: x_leftT[u][c] = sum_v P[v][u]*xr[v][c]; x_rightT = sum_v Qm[v][u]*xl[v][c]
  int ct = t & 15;
  int c0 = ct*4;
  float accL[8][4], accR[8][4];
  #pragma unroll
  for (int i = 0; i < 8; i++)
    #pragma unroll
    for (int j = 0; j < 4; j++) { accL[i][j] = 0.f; accR[i][j] = 0.f; }
  for (int v = 0; v < 128; v++) {
    float4 p1 = *(const float4*)&Cm[v*ST + u0];
    float4 p2 = *(const float4*)&Cm[v*ST + u0 + 4];
    float4 q1 = *(const float4*)&Bm[v*ST + u0];
    float4 q2 = *(const float4*)&Bm[v*ST + u0 + 4];
    float p[8] = {p1.x,p1.y,p1.z,p1.w,p2.x,p2.y,p2.z,p2.w};
    float q[8] = {q1.x,q1.y,q1.z,q1.w,q2.x,q2.y,q2.z,q2.w};
    float xrv[4], xlv[4];
    #pragma unroll
    for (int j = 0; j < 4; j++) { xrv[j] = xrs[v*XST + c0 + j]; xlv[j] = xls[v*XST + c0 + j]; }
    #pragma unroll
    for (int i = 0; i < 8; i++)
      #pragma unroll
      for (int j = 0; j < 4; j++) {
        accL[i][j] += p[i]*xrv[j];
        accR[i][j] += q[i]*xlv[j];
      }
  }
  __syncthreads();

  // blend in place (each (u,c) owned by exactly one thread)
  #pragma unroll
  for (int i = 0; i < 8; i++) {
    int u = u0 + i;
    float vl = Vl[u], vr = Vr[u];
    #pragma unroll
    for (int j = 0; j < 4; j++) {
      int c = c0 + j;
      float ol = xls[u*XST + c]*(1.f - vl) + accL[i][j]*vl;
      float orr = xrs[u*XST + c]*(1.f - vr) + accR[i][j]*vr;
      xls[u*XST + c] = ol;
      xrs[u*XST + c] = orr;
    }
  }
  __syncthreads();

  for (int i = t; i < 8192; i += 256) {
    int c = i >> 7, u = i & 127;
    size_t gi = ((size_t)(b*NC + c)*NH + h)*NW + u;
    outL[gi] = xls[u*XST + c];
    outR[gi] = xrs[u*XST + c];
  }
}

// ---------------- host ------------------------------------------------------
extern "C" void kernel_launch(void* const* d_in, const int* in_sizes, int n_in,
                              void* d_out, int out_size) {
  const float* xL    = (const float*)d_in[0];
  const float* xR    = (const float*)d_in[1];
  const float* gamma = (const float*)d_in[2];
  const float* beta  = (const float*)d_in[3];
  const float* w1    = (const float*)d_in[4];
  const float* b1    = (const float*)d_in[5];
  const float* w2    = (const float*)d_in[6];
  const float* b2    = (const float*)d_in[7];
  const float* qw    = (const float*)d_in[8];
  const float* qb    = (const float*)d_in[9];
  const float* kw    = (const float*)d_in[10];
  const float* kb    = (const float*)d_in[11];
  float* outL = (float*)d_out;
  float* outR = outL + (size_t)IMG;

  float *t1, *t2, *Qg, *Kg;
  cudaGetSymbolAddress((void**)&t1, g_t1);
  cudaGetSymbolAddress((void**)&t2, g_t2);
  cudaGetSymbolAddress((void**)&Qg, g_Q);
  cudaGetSymbolAddress((void**)&Kg, g_K);

  cudaFuncSetAttribute(conv3x3_kernel<true,false>,  cudaFuncAttributeMaxDynamicSharedMemorySize, CONV_SMEM);
  cudaFuncSetAttribute(conv3x3_kernel<false,true>,  cudaFuncAttributeMaxDynamicSharedMemorySize, CONV_SMEM);
  cudaFuncSetAttribute(qk_kernel,   cudaFuncAttributeMaxDynamicSharedMemorySize, QK_SMEM);
  cudaFuncSetAttribute(attn_kernel, cudaFuncAttributeMaxDynamicSharedMemorySize, ATTN_SMEM);

  bn_stats_kernel<<<128, 256>>>(xL, xR, gamma, beta);

  dim3 cgrid(NH/4, NB*NG);
  // left branch -> Q
  conv3x3_kernel<true,false><<<cgrid, 256, CONV_SMEM>>>(xL, nullptr, w1, b1, t1, 0);
  conv3x3_kernel<false,true><<<cgrid, 256, CONV_SMEM>>>(t1, xL, w2, b2, t2, 0);
  qk_kernel<<<NROW, 256, QK_SMEM>>>(t2, qw, qb, Qg);
  // right branch -> K
  conv3x3_kernel<true,false><<<cgrid, 256, CONV_SMEM>>>(xR, nullptr, w1, b1, t1, 1);
  conv3x3_kernel<false,true><<<cgrid, 256, CONV_SMEM>>>(t1, xR, w2, b2, t2, 1);
  qk_kernel<<<NROW, 256, QK_SMEM>>>(t2, kw, kb, Kg);
  // fused attention + blend
  attn_kernel<<<NROW, 256, ATTN_SMEM>>>(xL, xR, outL, outR);
}

// round 2
// speedup vs baseline: 1.4537x; 1.4537x over previous
#include <cuda_runtime.h>
#include <math.h>

#define NB 8
#define NC 64
#define NG 4
#define CG 16
#define NH 128
#define NW 128
#define HW (NH*NW)
#define IMG (NB*NC*HW)      // 8388608
#define NROW (NB*NH)        // 1024

// ---------------- scratch (device globals; no runtime allocation) ----------
__device__ float g_t1[2*(size_t)IMG];
__device__ float g_t2[2*(size_t)IMG];
__device__ float g_bnA[2][NC];
__device__ float g_bnB[2][NC];

// ---------------- BN statistics (training mode, per image) -----------------
__global__ __launch_bounds__(256) void bn_stats_kernel(
    const float* __restrict__ xl, const float* __restrict__ xr,
    const float* __restrict__ gamma, const float* __restrict__ beta) {
  int c = blockIdx.x & 63;
  int img = blockIdx.x >> 6;
  const float4* x = (const float4*)(img ? xr : xl);
  int t = threadIdx.x;
  float s = 0.f, s2 = 0.f;
  for (int b = 0; b < NB; b++) {
    const float4* p = x + (size_t)(b*NC + c)*(HW/4);
    for (int i = t; i < HW/4; i += 256) {
      float4 v = p[i];
      s  += v.x + v.y + v.z + v.w;
      s2 += v.x*v.x + v.y*v.y + v.z*v.z + v.w*v.w;
    }
  }
  __shared__ float sh[256], sh2[256];
  sh[t] = s; sh2[t] = s2; __syncthreads();
  for (int off = 128; off; off >>= 1) {
    if (t < off) { sh[t] += sh[t+off]; sh2[t] += sh2[t+off]; }
    __syncthreads();
  }
  if (t == 0) {
    const float inv = 1.f / (float)(NB*HW);
    float mean = sh[0] * inv;
    float var  = sh2[0] * inv - mean*mean;
    float a = gamma[c] * rsqrtf(var + 1e-5f);
    g_bnA[img][c] = a;
    g_bnB[img][c] = beta[c] - mean * a;
  }
}

// ---------------- grouped 3x3 conv (both images in one launch) -------------
// FIRST: conv1 of resb: BN applied to input at staging, LeakyReLU(0.1) on out
// !FIRST: conv2 of resb: adds bias + BN(x_orig) residual
#define IN_ST 132
#define CONV_SMEM ((CG*6*IN_ST + CG*CG*9)*4)

template<bool FIRST>
__global__ __launch_bounds__(256, 3) void conv3x3_kernel(
    const float* __restrict__ xL, const float* __restrict__ xR,
    float* __restrict__ t1, float* __restrict__ t2,
    const float* __restrict__ wgt, const float* __restrict__ bias) {
  extern __shared__ float sm[];
  float* in_s = sm;                 // [16ic][6r][132]
  float* w_s  = sm + CG*6*IN_ST;    // [ic][kh][kw][16oc]
  int t = threadIdx.x;
  int img = blockIdx.z;
  int b = blockIdx.y >> 2, g = blockIdx.y & 3;
  int h0 = blockIdx.x * 4;
  const float* xorig = img ? xR : xL;
  const float* xin = FIRST ? xorig : (t1 + (size_t)img*IMG);
  float* out = (FIRST ? t1 : t2) + (size_t)img*IMG;

  // weight restage: [oc][ic][3][3] -> [ic][kh][kw][oc]
  for (int i = t; i < CG*CG*9; i += 256) {
    int oc = i / 144, r = i - oc*144;
    w_s[r*16 + oc] = wgt[g*CG*CG*9 + i];
  }

  for (int i = t; i < CG*6*IN_ST; i += 256) {
    int ic  = i / (6*IN_ST);
    int rem = i - ic*(6*IN_ST);
    int r   = rem / IN_ST;
    int wc  = rem - r*IN_ST;
    int hh  = h0 - 1 + r;
    int ww  = wc - 1;
    float v = 0.f;
    if ((unsigned)hh < (unsigned)NH && (unsigned)ww < (unsigned)NW) {
      v = xin[((size_t)(b*NC + g*CG + ic)*NH + hh)*NW + ww];
      if (FIRST) v = g_bnA[img][g*CG+ic]*v + g_bnB[img][g*CG+ic];
    }
    in_s[i] = v;
  }
  __syncthreads();

  int wseg = t & 15, hh2 = (t >> 4) & 3, ocq = t >> 6;
  int w0 = wseg * 8, oc0 = ocq * 4;
  float acc[4][8];
  #pragma unroll
  for (int o = 0; o < 4; o++) {
    float bz = bias[g*CG + oc0 + o];
    #pragma unroll
    for (int j = 0; j < 8; j++) acc[o][j] = bz;
  }

  for (int ic = 0; ic < CG; ic++) {
    const float* base = in_s + (ic*6 + hh2)*IN_ST + w0;
    #pragma unroll
    for (int kh = 0; kh < 3; kh++) {
      const float* row = base + kh*IN_ST;
      float4 A  = *(const float4*)row;
      float4 B4 = *(const float4*)(row + 4);
      float in[10] = {A.x,A.y,A.z,A.w,B4.x,B4.y,B4.z,B4.w,row[8],row[9]};
      #pragma unroll
      for (int kw = 0; kw < 3; kw++) {
        float4 wv = *(const float4*)&w_s[((ic*3+kh)*3 + kw)*16 + oc0];
        float w4[4] = {wv.x,wv.y,wv.z,wv.w};
        #pragma unroll
        for (int o = 0; o < 4; o++)
          #pragma unroll
          for (int j = 0; j < 8; j++)
            acc[o][j] += w4[o]*in[kw+j];
      }
    }
  }

  int hout = h0 + hh2;
  #pragma unroll
  for (int o = 0; o < 4; o++) {
    int ch = g*CG + oc0 + o;
    size_t idx = ((size_t)(b*NC + ch)*NH + hout)*NW + w0;
    float r[8];
    if (FIRST) {
      #pragma unroll
      for (int j = 0; j < 8; j++) {
        float v = acc[o][j];
        r[j] = v > 0.f ? v : 0.1f*v;
      }
    } else {
      float ra = g_bnA[img][ch], rb = g_bnB[img][ch];
      float4 x0 = *(const float4*)&xorig[idx];
      float4 x1 = *(const float4*)&xorig[idx + 4];
      float xs[8] = {x0.x,x0.y,x0.z,x0.w,x1.x,x1.y,x1.z,x1.w};
      #pragma unroll
      for (int j = 0; j < 8; j++) r[j] = acc[o][j] + ra*xs[j] + rb;
    }
    *(float4*)&out[idx]     = make_float4(r[0],r[1],r[2],r[3]);
    *(float4*)&out[idx + 4] = make_float4(r[4],r[5],r[6],r[7]);
  }
}

// ---------------- fused: QK 1x1 conv + mean-sub + attention + blend --------
#define ST 128
#define XST 68
#define OFF_BM    16384
#define OFF_XLS   32768
#define OFF_XRS   41472
#define OFF_WS    50176
#define OFF_BS    52224
#define OFF_RMAX  52352
#define OFF_RSUMI 52480
#define OFF_CMAX  52608
#define OFF_CSUMI 52736
#define OFF_VL    52864
#define OFF_VR    52992
#define OFF_PART  53120
#define ATTN_SMEM ((53120 + 512)*4)   // 214528 B

__global__ __launch_bounds__(512, 1) void attn_kernel(
    const float* __restrict__ t2, const float* __restrict__ xL,
    const float* __restrict__ xR,
    const float* __restrict__ qw, const float* __restrict__ qb,
    const float* __restrict__ kw_, const float* __restrict__ kb,
    float* __restrict__ outL, float* __restrict__ outR) {
  extern __shared__ float sm[];
  float* Am    = sm;               // t2 stage -> S -> M_rl (row-major)
  float* Bm    = sm + OFF_BM;      // Q/K (k-major) -> M_lr^T
  float* xls   = sm + OFF_XLS;     // [v][c] stride 68
  float* xrs   = sm + OFF_XRS;
  float* ws    = sm + OFF_WS;      // [128k][16ic]
  float* bs    = sm + OFF_BS;
  float* rmax  = sm + OFF_RMAX;
  float* rsumI = sm + OFF_RSUMI;
  float* cmax  = sm + OFF_CMAX;
  float* csumI = sm + OFF_CSUMI;
  float* Vl    = sm + OFF_VL;
  float* Vr    = sm + OFF_VR;
  float* part  = sm + OFF_PART;
  int n = blockIdx.x, b = n >> 7, h = n & 127;
  int t = threadIdx.x, warp = t >> 5, lane = t & 31;

  // stage weights/bias + both t2 rows: Am[c][u], c<64 left, c>=64 right
  for (int i = t; i < 2048; i += 512) ws[i] = (i < 1024) ? qw[i] : kw_[i-1024];
  if (t < 128) bs[t] = (t < 64) ? qb[t] : kb[t-64];
  for (int i = t; i < 16384; i += 512) {
    int c = i >> 7, u = i & 127;
    size_t gi = ((c >= 64) ? (size_t)IMG : 0) +
                ((size_t)(b*NC + (c & 63))*NH + h)*NW + u;
    Am[c*ST + u] = t2[gi];
  }
  __syncthreads();

  // 1x1 grouped conv: Bm[k][u]  (k<64: Q channels, k>=64: K channels)
  for (int i = t; i < 16384; i += 512) {
    int k = i >> 7, u = i & 127;
    int cb = (k >> 4) * 16;
    float a = bs[k];
    #pragma unroll
    for (int ic = 0; ic < 16; ic++) a += ws[k*16 + ic] * Am[(cb + ic)*ST + u];
    Bm[i] = a;
  }
  __syncthreads();

  // row-mean subtract (mean over w per channel)
  for (int r = warp; r < 128; r += 16) {
    float s = 0.f;
    for (int u = lane; u < 128; u += 32) s += Bm[r*ST + u];
    #pragma unroll
    for (int off = 16; off; off >>= 1) s += __shfl_xor_sync(0xffffffffu, s, off);
    float mean = s * (1.f/128.f);
    for (int u = lane; u < 128; u += 32) Bm[r*ST + u] -= mean;
  }
  __syncthreads();

  // GEMM1: S[u][v] = sum_k Q[k][u]*K[k][v]  -> Am
  {
    int u0 = (t >> 5) * 8, v0 = (t & 31) * 4;
    float acc[8][4];
    #pragma unroll
    for (int i = 0; i < 8; i++)
      #pragma unroll
      for (int j = 0; j < 4; j++) acc[i][j] = 0.f;
    #pragma unroll 2
    for (int k = 0; k < 64; k++) {
      float4 qa = *(const float4*)&Bm[k*ST + u0];
      float4 qb4 = *(const float4*)&Bm[k*ST + u0 + 4];
      float4 kv = *(const float4*)&Bm[(64+k)*ST + v0];
      float qv[8] = {qa.x,qa.y,qa.z,qa.w,qb4.x,qb4.y,qb4.z,qb4.w};
      #pragma unroll
      for (int i = 0; i < 8; i++) {
        acc[i][0] += qv[i]*kv.x; acc[i][1] += qv[i]*kv.y;
        acc[i][2] += qv[i]*kv.z; acc[i][3] += qv[i]*kv.w;
      }
    }
    #pragma unroll
    for (int i = 0; i < 8; i++)
      *(float4*)&Am[(u0+i)*ST + v0] = make_float4(acc[i][0],acc[i][1],acc[i][2],acc[i][3]);
  }
  __syncthreads();

  // softmax stats + x staging (warp-specialized)
  if (warp < 8) {                     // row stats (M_rl)
    for (int r = warp*16; r < warp*16 + 16; r++) {
      float m = -1e30f;
      for (int j = lane; j < 128; j += 32) m = fmaxf(m, Am[r*ST + j]);
      #pragma unroll
      for (int off = 16; off; off >>= 1) m = fmaxf(m, __shfl_xor_sync(0xffffffffu, m, off));
      float s = 0.f;
      for (int j = lane; j < 128; j += 32) s += __expf(Am[r*ST + j] - m);
      #pragma unroll
      for (int off = 16; off; off >>= 1) s += __shfl_xor_sync(0xffffffffu, s, off);
      if (lane == 0) { rmax[r] = m; rsumI[r] = 1.f/s; }
    }
  } else if (warp < 12) {             // column stats (M_lr)
    int col = (warp - 8)*32 + lane;
    float m0=-1e30f, m1=-1e30f, m2=-1e30f, m3=-1e30f;
    for (int r = 0; r < 128; r += 4) {
      m0 = fmaxf(m0, Am[(r+0)*ST + col]);
      m1 = fmaxf(m1, Am[(r+1)*ST + col]);
      m2 = fmaxf(m2, Am[(r+2)*ST + col]);
      m3 = fmaxf(m3, Am[(r+3)*ST + col]);
    }
    float m = fmaxf(fmaxf(m0,m1), fmaxf(m2,m3));
    float s0=0.f, s1=0.f, s2=0.f, s3=0.f;
    for (int r = 0; r < 128; r += 4) {
      s0 += __expf(Am[(r+0)*ST + col] - m);
      s1 += __expf(Am[(r+1)*ST + col] - m);
      s2 += __expf(Am[(r+2)*ST + col] - m);
      s3 += __expf(Am[(r+3)*ST + col] - m);
    }
    cmax[col] = m; csumI[col] = 1.f/(s0+s1+s2+s3);
  } else {                            // stage original x rows [v][c]
    for (int i = t - 384; i < 8192; i += 128) {
      int c = i >> 7, v = i & 127;
      size_t gi = ((size_t)(b*NC + c)*NH + h)*NW + v;
      xls[v*XST + c] = xL[gi];
      xrs[v*XST + c] = xR[gi];
    }
  }
  __syncthreads();

  // elementwise: Am = M_rl (row-major), Bm = M_lr^T
  for (int i = t; i < 16384; i += 512) {
    int r = i >> 7, c = i & 127;
    float s = Am[i];
    Am[i] = __expf(s - rmax[r]) * rsumI[r];
    Bm[i] = __expf(s - cmax[c]) * csumI[c];
  }
  __syncthreads();

  // V_left[u] = sum_v (sum_d M_rl[u+d][v]) * M_lr[v][u]   (lane = v, contiguous)
  for (int u = warp; u < 128; u += 16) {
    float acc = 0.f;
    for (int v = lane; v < 128; v += 32) {
      float s5 = 0.f;
      #pragma unroll
      for (int d = -2; d <= 2; d++) {
        int ui = u + d;
        if ((unsigned)ui < 128u) s5 += Am[ui*ST + v];
      }
      acc += s5 * Bm[u*ST + v];
    }
    #pragma unroll
    for (int off = 16; off; off >>= 1) acc += __shfl_xor_sync(0xffffffffu, acc, off);
    if (lane == 0) Vl[u] = tanhf(5.f*acc);
  }
  // V_right[u] = sum_v M_rl[v][u] * (sum_d M_lr[u+d][v])  (lane = u, contiguous)
  {
    int u = (warp & 3)*32 + lane;
    int v0 = (warp >> 2)*32;
    float acc = 0.f;
    for (int v = v0; v < v0 + 32; v++) {
      float amv = Am[v*ST + u];
      float s5 = 0.f;
      #pragma unroll
      for (int d = -2; d <= 2; d++) {
        int ui = u + d;
        if ((unsigned)ui < 128u) s5 += Bm[v*ST + ui];
      }
      acc += amv * s5;
    }
    part[(warp >> 2)*128 + u] = acc;
  }
  __syncthreads();
  if (t < 128) Vr[t] = tanhf(5.f*(part[t] + part[128+t] + part[256+t] + part[384+t]));

  // GEMM2 (threads 0-255): x_leftT[u][c] = sum_v M_rl[u][v]*xr[v][c]
  // GEMM3 (threads 256-511): x_rightT[u][c] = sum_v M_lr[u][v]*xl[v][c]
  int group = t >> 8;
  int tid = t & 255;
  int c0 = (tid & 15)*4, u0 = (tid >> 4)*8;
  float acc[8][4];
  #pragma unroll
  for (int i = 0; i < 8; i++)
    #pragma unroll
    for (int j = 0; j < 4; j++) acc[i][j] = 0.f;

  if (group == 0) {
    for (int v0g = 0; v0g < 128; v0g += 4) {
      float4 x0 = *(const float4*)&xrs[(v0g+0)*XST + c0];
      float4 x1 = *(const float4*)&xrs[(v0g+1)*XST + c0];
      float4 x2 = *(const float4*)&xrs[(v0g+2)*XST + c0];
      float4 x3 = *(const float4*)&xrs[(v0g+3)*XST + c0];
      #pragma unroll
      for (int i = 0; i < 8; i++) {
        float4 m = *(const float4*)&Am[(u0+i)*ST + v0g];
        acc[i][0] += m.x*x0.x + m.y*x1.x + m.z*x2.x + m.w*x3.x;
        acc[i][1] += m.x*x0.y + m.y*x1.y + m.z*x2.y + m.w*x3.y;
        acc[i][2] += m.x*x0.z + m.y*x1.z + m.z*x2.z + m.w*x3.z;
        acc[i][3] += m.x*x0.w + m.y*x1.w + m.z*x2.w + m.w*x3.w;
      }
    }
  } else {
    for (int v = 0; v < 128; v++) {
      float4 xv = *(const float4*)&xls[v*XST + c0];
      float4 b0 = *(const float4*)&Bm[v*ST + u0];
      float4 b1 = *(const float4*)&Bm[v*ST + u0 + 4];
      float bu[8] = {b0.x,b0.y,b0.z,b0.w,b1.x,b1.y,b1.z,b1.w};
      #pragma unroll
      for (int i = 0; i < 8; i++) {
        acc[i][0] += bu[i]*xv.x; acc[i][1] += bu[i]*xv.y;
        acc[i][2] += bu[i]*xv.z; acc[i][3] += bu[i]*xv.w;
      }
    }
  }
  __syncthreads();

  // blend in place
  if (group == 0) {
    #pragma unroll
    for (int i = 0; i < 8; i++) {
      int u = u0 + i;
      float vl = Vl[u];
      #pragma unroll
      for (int cc = 0; cc < 4; cc++) {
        int x = u*XST + c0 + cc;
        xls[x] = xls[x]*(1.f - vl) + acc[i][cc]*vl;
      }
    }
  } else {
    #pragma unroll
    for (int i = 0; i < 8; i++) {
      int u = u0 + i;
      float vr = Vr[u];
      #pragma unroll
      for (int cc = 0; cc < 4; cc++) {
        int x = u*XST + c0 + cc;
        xrs[x] = xrs[x]*(1.f - vr) + acc[i][cc]*vr;
      }
    }
  }
  __syncthreads();

  for (int i = t; i < 8192; i += 512) {
    int c = i >> 7, u = i & 127;
    size_t gi = ((size_t)(b*NC + c)*NH + h)*NW + u;
    outL[gi] = xls[u*XST + c];
    outR[gi] = xrs[u*XST + c];
  }
}

// ---------------- host ------------------------------------------------------
extern "C" void kernel_launch(void* const* d_in, const int* in_sizes, int n_in,
                              void* d_out, int out_size) {
  const float* xL    = (const float*)d_in[0];
  const float* xR    = (const float*)d_in[1];
  const float* gamma = (const float*)d_in[2];
  const float* beta  = (const float*)d_in[3];
  const float* w1    = (const float*)d_in[4];
  const float* b1    = (const float*)d_in[5];
  const float* w2    = (const float*)d_in[6];
  const float* b2    = (const float*)d_in[7];
  const float* qw    = (const float*)d_in[8];
  const float* qb    = (const float*)d_in[9];
  const float* kw    = (const float*)d_in[10];
  const float* kb    = (const float*)d_in[11];
  float* outL = (float*)d_out;
  float* outR = outL + (size_t)IMG;

  float *t1, *t2;
  cudaGetSymbolAddress((void**)&t1, g_t1);
  cudaGetSymbolAddress((void**)&t2, g_t2);

  cudaFuncSetAttribute(conv3x3_kernel<true>,  cudaFuncAttributeMaxDynamicSharedMemorySize, CONV_SMEM);
  cudaFuncSetAttribute(conv3x3_kernel<false>, cudaFuncAttributeMaxDynamicSharedMemorySize, CONV_SMEM);
  cudaFuncSetAttribute(attn_kernel, cudaFuncAttributeMaxDynamicSharedMemorySize, ATTN_SMEM);

  bn_stats_kernel<<<128, 256>>>(xL, xR, gamma, beta);

  dim3 cgrid(NH/4, NB*NG, 2);
  conv3x3_kernel<true ><<<cgrid, 256, CONV_SMEM>>>(xL, xR, t1, t2, w1, b1);
  conv3x3_kernel<false><<<cgrid, 256, CONV_SMEM>>>(xL, xR, t1, t2, w2, b2);

  attn_kernel<<<NROW, 512, ATTN_SMEM>>>(t2, xL, xR, qw, qb, kw, kb, outL, outR);
}

// round 3
// speedup vs baseline: 1.5168x; 1.0434x over previous
#include <cuda_runtime.h>
#include <math.h>

#define NB 8
#define NC 64
#define NG 4
#define CG 16
#define NH 128
#define NW 128
#define HW (NH*NW)
#define IMG (NB*NC*HW)
#define NROW (NB*NH)

typedef unsigned long long u64;

__device__ __forceinline__ u64 f2dup(float v) {
  u64 r; asm("mov.b64 %0, {%1, %1};" : "=l"(r) : "f"(v)); return r;
}
__device__ __forceinline__ u64 f2pk(float a, float b) {
  u64 r; asm("mov.b64 %0, {%1, %2};" : "=l"(r) : "f"(a), "f"(b)); return r;
}
__device__ __forceinline__ void fma2(u64& d, u64 a, u64 b) {
  asm("fma.rn.f32x2 %0, %1, %2, %0;" : "+l"(d) : "l"(a), "l"(b));
}
__device__ __forceinline__ float2 f2up(u64 v) {
  float2 f; asm("mov.b64 {%0, %1}, %2;" : "=f"(f.x), "=f"(f.y) : "l"(v)); return f;
}

// ---------------- scratch ----------------------------------------------------
__device__ float g_t1[2*(size_t)IMG];
__device__ float g_t2[2*(size_t)IMG];
__device__ float g_bnA[2][NC];
__device__ float g_bnB[2][NC];

// ---------------- BN statistics ----------------------------------------------
__global__ __launch_bounds__(256) void bn_stats_kernel(
    const float* __restrict__ xl, const float* __restrict__ xr,
    const float* __restrict__ gamma, const float* __restrict__ beta) {
  int c = blockIdx.x & 63;
  int img = blockIdx.x >> 6;
  const float4* x = (const float4*)(img ? xr : xl);
  int t = threadIdx.x;
  float s = 0.f, s2 = 0.f;
  for (int b = 0; b < NB; b++) {
    const float4* p = x + (size_t)(b*NC + c)*(HW/4);
    for (int i = t; i < HW/4; i += 256) {
      float4 v = p[i];
      s  += v.x + v.y + v.z + v.w;
      s2 += v.x*v.x + v.y*v.y + v.z*v.z + v.w*v.w;
    }
  }
  __shared__ float sh[256], sh2[256];
  sh[t] = s; sh2[t] = s2; __syncthreads();
  for (int off = 128; off; off >>= 1) {
    if (t < off) { sh[t] += sh[t+off]; sh2[t] += sh2[t+off]; }
    __syncthreads();
  }
  if (t == 0) {
    const float inv = 1.f / (float)(NB*HW);
    float mean = sh[0] * inv;
    float var  = sh2[0] * inv - mean*mean;
    float a = gamma[c] * rsqrtf(var + 1e-5f);
    g_bnA[img][c] = a;
    g_bnB[img][c] = beta[c] - mean * a;
  }
}

// ---------------- grouped 3x3 conv (f32x2 packed over oc) --------------------
#define IN_ST 132
#define CONV_SMEM ((CG*6*IN_ST + CG*CG*9)*4)

template<bool FIRST>
__global__ __launch_bounds__(256, 2) void conv3x3_kernel(
    const float* __restrict__ xL, const float* __restrict__ xR,
    float* __restrict__ t1, float* __restrict__ t2,
    const float* __restrict__ wgt, const float* __restrict__ bias) {
  extern __shared__ float sm[];
  float* in_s = sm;                 // [16ic][6r][132]
  float* w_s  = sm + CG*6*IN_ST;    // [ic][kh][kw][16oc]
  int t = threadIdx.x;
  int img = blockIdx.z;
  int b = blockIdx.y >> 2, g = blockIdx.y & 3;
  int h0 = blockIdx.x * 4;
  const float* xorig = img ? xR : xL;
  const float* xin = FIRST ? xorig : (t1 + (size_t)img*IMG);
  float* out = (FIRST ? t1 : t2) + (size_t)img*IMG;

  for (int i = t; i < CG*CG*9; i += 256) {
    int oc = i / 144, r = i - oc*144;
    w_s[r*16 + oc] = wgt[g*CG*CG*9 + i];
  }
  for (int i = t; i < CG*6*IN_ST; i += 256) {
    int ic  = i / (6*IN_ST);
    int rem = i - ic*(6*IN_ST);
    int r   = rem / IN_ST;
    int wc  = rem - r*IN_ST;
    int hh  = h0 - 1 + r;
    int ww  = wc - 1;
    float v = 0.f;
    if ((unsigned)hh < (unsigned)NH && (unsigned)ww < (unsigned)NW) {
      v = xin[((size_t)(b*NC + g*CG + ic)*NH + hh)*NW + ww];
      if (FIRST) v = g_bnA[img][g*CG+ic]*v + g_bnB[img][g*CG+ic];
    }
    in_s[i] = v;
  }
  __syncthreads();

  int wseg = t & 15, hh2 = (t >> 4) & 3, ocq = t >> 6;
  int w0 = wseg * 8, oc0 = ocq * 4;

  // acc2[p][j]: oc pair p (oc0+2p, oc0+2p+1), output column j
  u64 acc2[2][8];
  {
    u64 bz0 = f2pk(bias[g*CG+oc0],   bias[g*CG+oc0+1]);
    u64 bz1 = f2pk(bias[g*CG+oc0+2], bias[g*CG+oc0+3]);
    #pragma unroll
    for (int j = 0; j < 8; j++) { acc2[0][j] = bz0; acc2[1][j] = bz1; }
  }

  for (int ic = 0; ic < CG; ic++) {
    const float* base = in_s + (ic*6 + hh2)*IN_ST + w0;
    #pragma unroll
    for (int kh = 0; kh < 3; kh++) {
      const float* row = base + kh*IN_ST;
      float4 A  = *(const float4*)row;
      float4 B4 = *(const float4*)(row + 4);
      float2 C2 = *(const float2*)(row + 8);
      float in[10] = {A.x,A.y,A.z,A.w,B4.x,B4.y,B4.z,B4.w,C2.x,C2.y};
      u64 ind[10];
      #pragma unroll
      for (int j = 0; j < 10; j++) ind[j] = f2dup(in[j]);
      #pragma unroll
      for (int kw = 0; kw < 3; kw++) {
        ulonglong2 wp = *(const ulonglong2*)&w_s[((ic*3+kh)*3 + kw)*16 + oc0];
        #pragma unroll
        for (int j = 0; j < 8; j++) {
          fma2(acc2[0][j], ind[kw+j], wp.x);
          fma2(acc2[1][j], ind[kw+j], wp.y);
        }
      }
    }
  }

  int hout = h0 + hh2;
  #pragma unroll
  for (int o = 0; o < 4; o++) {
    int ch = g*CG + oc0 + o;
    size_t idx = ((size_t)(b*NC + ch)*NH + hout)*NW + w0;
    float r[8];
    #pragma unroll
    for (int j = 0; j < 8; j++) {
      float2 f = f2up(acc2[o>>1][j]);
      r[j] = (o & 1) ? f.y : f.x;
    }
    if (FIRST) {
      #pragma unroll
      for (int j = 0; j < 8; j++) r[j] = r[j] > 0.f ? r[j] : 0.1f*r[j];
    } else {
      float ra = g_bnA[img][ch], rb = g_bnB[img][ch];
      float4 x0 = *(const float4*)&xorig[idx];
      float4 x1 = *(const float4*)&xorig[idx + 4];
      float xs[8] = {x0.x,x0.y,x0.z,x0.w,x1.x,x1.y,x1.z,x1.w};
      #pragma unroll
      for (int j = 0; j < 8; j++) r[j] = r[j] + ra*xs[j] + rb;
    }
    *(float4*)&out[idx]     = make_float4(r[0],r[1],r[2],r[3]);
    *(float4*)&out[idx + 4] = make_float4(r[4],r[5],r[6],r[7]);
  }
}

// ---------------- fused attention ---------------------------------------------
#define ST 128
#define XST 68
#define OFF_BM    16384
#define OFF_XLS   32768
#define OFF_XRS   41472
#define OFF_WS    50176
#define OFF_BS    52224
#define OFF_RMAX  52352
#define OFF_RSUMI 52480
#define OFF_CMAX  52608
#define OFF_CSUMI 52736
#define OFF_VL    52864
#define OFF_VR    52992
#define OFF_PART  53120
#define ATTN_SMEM ((53120 + 2048)*4)   // 220672 B

__global__ __launch_bounds__(512, 1) void attn_kernel(
    const float* __restrict__ t2, const float* __restrict__ xL,
    const float* __restrict__ xR,
    const float* __restrict__ qw, const float* __restrict__ qb,
    const float* __restrict__ kw_, const float* __restrict__ kb,
    float* __restrict__ outL, float* __restrict__ outR) {
  extern __shared__ float sm[];
  float* Am    = sm;               // t2 stage -> S -> E_rl (row-major, unnormalized)
  float* Bm    = sm + OFF_BM;      // Q/K (k-major) -> E_lr^T (unnormalized)
  float* xls   = sm + OFF_XLS;     // [v][c] stride 68
  float* xrs   = sm + OFF_XRS;
  float* ws    = sm + OFF_WS;
  float* bs    = sm + OFF_BS;
  float* rmax  = sm + OFF_RMAX;
  float* rsumI = sm + OFF_RSUMI;
  float* cmax  = sm + OFF_CMAX;
  float* csumI = sm + OFF_CSUMI;
  float* Vl    = sm + OFF_VL;
  float* Vr    = sm + OFF_VR;
  float* part  = sm + OFF_PART;    // 2048
  int n = blockIdx.x, b = n >> 7, h = n & 127;
  int t = threadIdx.x, warp = t >> 5, lane = t & 31;

  // stage weights/bias + both t2 rows
  for (int i = t; i < 2048; i += 512) ws[i] = (i < 1024) ? qw[i] : kw_[i-1024];
  if (t < 128) bs[t] = (t < 64) ? qb[t] : kb[t-64];
  for (int i = t; i < 16384; i += 512) {
    int c = i >> 7, u = i & 127;
    size_t gi = ((c >= 64) ? (size_t)IMG : 0) +
                ((size_t)(b*NC + (c & 63))*NH + h)*NW + u;
    Am[c*ST + u] = t2[gi];
  }
  __syncthreads();

  // 1x1 grouped conv (f32x2, pairs over u): Bm[k][u]
  for (int i = t; i < 8192; i += 512) {
    int k = i >> 6, up = (i & 63)*2;
    int cb = (k >> 4) * 16;
    float bzv = bs[k];
    u64 a = f2pk(bzv, bzv);
    #pragma unroll
    for (int ic = 0; ic < 16; ic++) {
      u64 w2 = f2dup(ws[k*16 + ic]);
      u64 xp = *(const u64*)&Am[(cb + ic)*ST + up];
      fma2(a, w2, xp);
    }
    *(u64*)&Bm[k*ST + up] = a;
  }
  __syncthreads();

  // row-mean subtract
  for (int r = warp; r < 128; r += 16) {
    float s = 0.f;
    for (int u = lane; u < 128; u += 32) s += Bm[r*ST + u];
    #pragma unroll
    for (int off = 16; off; off >>= 1) s += __shfl_xor_sync(0xffffffffu, s, off);
    float mean = s * (1.f/128.f);
    for (int u = lane; u < 128; u += 32) Bm[r*ST + u] -= mean;
  }
  __syncthreads();

  // GEMM1: S[u][v] = sum_k Q[k][u]*K[k][v]  (f32x2 pairs over v)
  {
    int u0 = (t >> 5) * 8, v0 = (t & 31) * 4;
    u64 acc2[8][2];
    #pragma unroll
    for (int i = 0; i < 8; i++) { acc2[i][0] = 0ull; acc2[i][1] = 0ull; }
    for (int k = 0; k < 64; k++) {
      float4 qa  = *(const float4*)&Bm[k*ST + u0];
      float4 qb4 = *(const float4*)&Bm[k*ST + u0 + 4];
      ulonglong2 kv = *(const ulonglong2*)&Bm[(64+k)*ST + v0];
      float qv[8] = {qa.x,qa.y,qa.z,qa.w,qb4.x,qb4.y,qb4.z,qb4.w};
      #pragma unroll
      for (int i = 0; i < 8; i++) {
        u64 qd = f2dup(qv[i]);
        fma2(acc2[i][0], qd, kv.x);
        fma2(acc2[i][1], qd, kv.y);
      }
    }
    #pragma unroll
    for (int i = 0; i < 8; i++) {
      float2 a = f2up(acc2[i][0]), c = f2up(acc2[i][1]);
      *(float4*)&Am[(u0+i)*ST + v0] = make_float4(a.x,a.y,c.x,c.y);
    }
  }
  __syncthreads();

  // Phase A: maxes only + x staging (warp-specialized)
  if (warp < 8) {                     // row maxes
    for (int r = warp*16; r < warp*16 + 16; r++) {
      float m = -1e30f;
      for (int j = lane; j < 128; j += 32) m = fmaxf(m, Am[r*ST + j]);
      #pragma unroll
      for (int off = 16; off; off >>= 1) m = fmaxf(m, __shfl_xor_sync(0xffffffffu, m, off));
      if (lane == 0) rmax[r] = m;
    }
  } else if (warp < 12) {             // column maxes
    int col = (warp - 8)*32 + lane;
    float m0=-1e30f, m1=-1e30f, m2=-1e30f, m3=-1e30f;
    for (int r = 0; r < 128; r += 4) {
      m0 = fmaxf(m0, Am[(r+0)*ST + col]);
      m1 = fmaxf(m1, Am[(r+1)*ST + col]);
      m2 = fmaxf(m2, Am[(r+2)*ST + col]);
      m3 = fmaxf(m3, Am[(r+3)*ST + col]);
    }
    cmax[col] = fmaxf(fmaxf(m0,m1), fmaxf(m2,m3));
  } else {                            // stage x rows [v][c]
    for (int i = t - 384; i < 8192; i += 128) {
      int c = i >> 7, v = i & 127;
      size_t gi = ((size_t)(b*NC + c)*NH + h)*NW + v;
      xls[v*XST + c] = xL[gi];
      xrs[v*XST + c] = xR[gi];
    }
  }
  __syncthreads();

  // Phase B: materialize E_rl (Am), E_lr^T (Bm) + row/col sums (one exp pair/elem)
  {
    float cm[4], csump[4];
    #pragma unroll
    for (int k = 0; k < 4; k++) { cm[k] = cmax[lane + k*32]; csump[k] = 0.f; }
    for (int rr = 0; rr < 8; rr++) {
      int r = warp*8 + rr;
      float rm = rmax[r];
      float rs = 0.f;
      #pragma unroll
      for (int k = 0; k < 4; k++) {
        int c = lane + k*32;
        float s = Am[r*ST + c];
        float erl = __expf(s - rm);
        float elr = __expf(s - cm[k]);
        Am[r*ST + c] = erl;
        Bm[r*ST + c] = elr;
        rs += erl;
        csump[k] += elr;
      }
      #pragma unroll
      for (int off = 16; off; off >>= 1) rs += __shfl_xor_sync(0xffffffffu, rs, off);
      if (lane == 0) rsumI[r] = 1.f / rs;
    }
    #pragma unroll
    for (int k = 0; k < 4; k++) part[warp*128 + k*32 + lane] = csump[k];
  }
  __syncthreads();
  if (t < 128) {
    float s = 0.f;
    #pragma unroll
    for (int w = 0; w < 16; w++) s += part[w*128 + t];
    csumI[t] = 1.f / s;
  }
  __syncthreads();

  // V_left[u] = sum_v (sum_d rsumI[u+d]*E_rl[u+d][v]) * E_lr^T[u][v]*csumI[v]
  for (int u = warp; u < 128; u += 16) {
    float rI[5];
    #pragma unroll
    for (int d = 0; d < 5; d++) {
      int ui = u + d - 2;
      rI[d] = ((unsigned)ui < 128u) ? rsumI[ui] : 0.f;
    }
    float acc = 0.f;
    for (int v = lane; v < 128; v += 32) {
      float s5 = 0.f;
      #pragma unroll
      for (int d = 0; d < 5; d++) {
        int ui = u + d - 2;
        if ((unsigned)ui < 128u) s5 += rI[d]*Am[ui*ST + v];
      }
      acc += s5 * Bm[u*ST + v] * csumI[v];
    }
    #pragma unroll
    for (int off = 16; off; off >>= 1) acc += __shfl_xor_sync(0xffffffffu, acc, off);
    if (lane == 0) Vl[u] = tanhf(5.f*acc);
  }
  // V_right[u] = sum_v E_rl[v][u]*rsumI[v] * (sum_d E_lr^T[v][u+d]*csumI[u+d])
  {
    int u = (warp & 3)*32 + lane;
    int v0 = (warp >> 2)*32;
    float ci[5];
    #pragma unroll
    for (int d = 0; d < 5; d++) {
      int ui = u + d - 2;
      ci[d] = ((unsigned)ui < 128u) ? csumI[ui] : 0.f;
    }
    float acc = 0.f;
    for (int v = v0; v < v0 + 32; v++) {
      float s5 = 0.f;
      #pragma unroll
      for (int d = 0; d < 5; d++) {
        int ui = u + d - 2;
        if ((unsigned)ui < 128u) s5 += Bm[v*ST + ui]*ci[d];
      }
      acc += Am[v*ST + u] * rsumI[v] * s5;
    }
    part[(warp >> 2)*128 + u] = acc;
  }
  __syncthreads();
  if (t < 128) Vr[t] = tanhf(5.f*(part[t] + part[128+t] + part[256+t] + part[384+t]));

  // GEMM2 (g0): xlT[u][c] = rsumI[u]*sum_v E_rl[u][v]*xr[v][c]
  // GEMM3 (g1): xrT[u][c] = csumI[u]*sum_v E_lr^T[v][u]*xl[v][c]
  int group = t >> 8;
  int tid = t & 255;
  int c0 = (tid & 15)*4, u0 = (tid >> 4)*8;
  u64 acc2[8][2];
  #pragma unroll
  for (int i = 0; i < 8; i++) { acc2[i][0] = 0ull; acc2[i][1] = 0ull; }

  if (group == 0) {
    for (int v0g = 0; v0g < 128; v0g += 4) {
      ulonglong2 x0 = *(const ulonglong2*)&xrs[(v0g+0)*XST + c0];
      ulonglong2 x1 = *(const ulonglong2*)&xrs[(v0g+1)*XST + c0];
      ulonglong2 x2 = *(const ulonglong2*)&xrs[(v0g+2)*XST + c0];
      ulonglong2 x3 = *(const ulonglong2*)&xrs[(v0g+3)*XST + c0];
      #pragma unroll
      for (int i = 0; i < 8; i++) {
        float4 m = *(const float4*)&Am[(u0+i)*ST + v0g];
        u64 m0 = f2dup(m.x), m1 = f2dup(m.y), m2 = f2dup(m.z), m3 = f2dup(m.w);
        fma2(acc2[i][0], m0, x0.x); fma2(acc2[i][1], m0, x0.y);
        fma2(acc2[i][0], m1, x1.x); fma2(acc2[i][1], m1, x1.y);
        fma2(acc2[i][0], m2, x2.x); fma2(acc2[i][1], m2, x2.y);
        fma2(acc2[i][0], m3, x3.x); fma2(acc2[i][1], m3, x3.y);
      }
    }
  } else {
    for (int v = 0; v < 128; v++) {
      ulonglong2 xp = *(const ulonglong2*)&xls[v*XST + c0];
      float4 b0 = *(const float4*)&Bm[v*ST + u0];
      float4 b1 = *(const float4*)&Bm[v*ST + u0 + 4];
      float bu[8] = {b0.x,b0.y,b0.z,b0.w,b1.x,b1.y,b1.z,b1.w};
      #pragma unroll
      for (int i = 0; i < 8; i++) {
        u64 bd = f2dup(bu[i]);
        fma2(acc2[i][0], bd, xp.x);
        fma2(acc2[i][1], bd, xp.y);
      }
    }
  }
  __syncthreads();

  // blend in place (normalization folded)
  if (group == 0) {
    #pragma unroll
    for (int i = 0; i < 8; i++) {
      int u = u0 + i;
      float vl = Vl[u];
      float gsc = vl * rsumI[u];
      float2 f0 = f2up(acc2[i][0]), f1 = f2up(acc2[i][1]);
      float xt[4] = {f0.x, f0.y, f1.x, f1.y};
      #pragma unroll
      for (int cc = 0; cc < 4; cc++) {
        int x = u*XST + c0 + cc;
        xls[x] = xls[x]*(1.f - vl) + xt[cc]*gsc;
      }
    }
  } else {
    #pragma unroll
    for (int i = 0; i < 8; i++) {
      int u = u0 + i;
      float vr = Vr[u];
      float gsc = vr * csumI[u];
      float2 f0 = f2up(acc2[i][0]), f1 = f2up(acc2[i][1]);
      float xt[4] = {f0.x, f0.y, f1.x, f1.y};
      #pragma unroll
      for (int cc = 0; cc < 4; cc++) {
        int x = u*XST + c0 + cc;
        xrs[x] = xrs[x]*(1.f - vr) + xt[cc]*gsc;
      }
    }
  }
  __syncthreads();

  for (int i = t; i < 8192; i += 512) {
    int c = i >> 7, u = i & 127;
    size_t gi = ((size_t)(b*NC + c)*NH + h)*NW + u;
    outL[gi] = xls[u*XST + c];
    outR[gi] = xrs[u*XST + c];
  }
}

// ---------------- host ------------------------------------------------------
extern "C" void kernel_launch(void* const* d_in, const int* in_sizes, int n_in,
                              void* d_out, int out_size) {
  const float* xL    = (const float*)d_in[0];
  const float* xR    = (const float*)d_in[1];
  const float* gamma = (const float*)d_in[2];
  const float* beta  = (const float*)d_in[3];
  const float* w1    = (const float*)d_in[4];
  const float* b1    = (const float*)d_in[5];
  const float* w2    = (const float*)d_in[6];
  const float* b2    = (const float*)d_in[7];
  const float* qw    = (const float*)d_in[8];
  const float* qb    = (const float*)d_in[9];
  const float* kw    = (const float*)d_in[10];
  const float* kb    = (const float*)d_in[11];
  float* outL = (float*)d_out;
  float* outR = outL + (size_t)IMG;

  float *t1, *t2;
  cudaGetSymbolAddress((void**)&t1, g_t1);
  cudaGetSymbolAddress((void**)&t2, g_t2);

  cudaFuncSetAttribute(conv3x3_kernel<true>,  cudaFuncAttributeMaxDynamicSharedMemorySize, CONV_SMEM);
  cudaFuncSetAttribute(conv3x3_kernel<false>, cudaFuncAttributeMaxDynamicSharedMemorySize, CONV_SMEM);
  cudaFuncSetAttribute(attn_kernel, cudaFuncAttributeMaxDynamicSharedMemorySize, ATTN_SMEM);

  bn_stats_kernel<<<128, 256>>>(xL, xR, gamma, beta);

  dim3 cgrid(NH/4, NB*NG, 2);
  conv3x3_kernel<true ><<<cgrid, 256, CONV_SMEM>>>(xL, xR, t1, t2, w1, b1);
  conv3x3_kernel<false><<<cgrid, 256, CONV_SMEM>>>(xL, xR, t1, t2, w2, b2);

  attn_kernel<<<NROW, 512, ATTN_SMEM>>>(t2, xL, xR, qw, qb, kw, kb, outL, outR);
}